// round 17
// speedup vs baseline: 9.8647x; 1.0223x over previous
#include <cuda_runtime.h>
#include <cuda_fp16.h>
#include <cstdint>
#include <math.h>
#include <stddef.h>

// Problem constants
#define B_   32
#define N_   8192
#define E_   1048576
#define BN_  (B_ * N_)          // 262144
#define L_   2

// ---------------------------------------------------------------------------
// Arch-feature gate (tcgen05 only exists on sm_100a/sm_103a passes)
// ---------------------------------------------------------------------------
#if defined(__CUDA_ARCH_FEAT_SM103_ALL) || defined(__CUDA_ARCH_FEAT_SM100_ALL)
#  define TC_AVAIL 1
#endif
#ifndef TC_AVAIL
#  ifdef __CUDA_ARCH_HAS_FEATURE__
#    if __CUDA_ARCH_HAS_FEATURE__(SM103_ALL) || __CUDA_ARCH_HAS_FEATURE__(SM100_ALL)
#      define TC_AVAIL 1
#    endif
#  endif
#endif
#ifndef TC_AVAIL
#  define TC_AVAIL 0
#endif

// ---------------------------------------------------------------------------
// Scratch (static device globals)
// ---------------------------------------------------------------------------
static __device__ __align__(16) __half g_h [(size_t)BN_ * 128];
static __device__ __align__(16) __half g_b1[(size_t)BN_ * 128];   // msg_all
static __device__ __align__(16) __half g_b2[(size_t)BN_ * 128];   // agg
static __device__ __align__(16) float  g_wt [12544];              // fp32 W_in^T + bse/bhe
static __device__ __align__(16) __half g_wth[147456];             // fp16 weights
static __device__ int g_off [BN_ + 1];
static __device__ int g_part[512];
static __device__ int g_cur [BN_];
static __device__ int g_srcl[E_];

// g_wt fp32 offsets
#define O_WIN   0        // 128 x 96 (K=67 pad)
#define O_BSE   12288
#define O_BHE   12416
// g_wth half offsets
#define H_MSG0  0        // 128x128
#define H_MSG1  16384
#define H_UPD0  32768    // 128x256
#define H_UPD1  65536
#define H_WSE   98304    // 128x192 (K=131 pad)
#define H_WHE   122880

// ---------------------------------------------------------------------------
// Helpers
// ---------------------------------------------------------------------------
__device__ __forceinline__ uint32_t smem_u32(const void* p) {
    uint32_t a;
    asm("{ .reg .u64 t; cvta.to.shared.u64 t, %1; cvt.u32.u64 %0, t; }"
        : "=r"(a) : "l"(p));
    return a;
}

#define SW128(o) ((o) ^ (((o) >> 3) & 0x70))

__device__ __forceinline__ void cp16(uint32_t dst, const void* src) {
    asm volatile("cp.async.cg.shared.global [%0], [%1], 16;"
                 :: "r"(dst), "l"(src) : "memory");
}
__device__ __forceinline__ void cp_commit() {
    asm volatile("cp.async.commit_group;" ::: "memory");
}
__device__ __forceinline__ void cp_wait1() {
    asm volatile("cp.async.wait_group 1;" ::: "memory");
}
__device__ __forceinline__ void cp_wait0() {
    asm volatile("cp.async.wait_group 0;" ::: "memory");
}
__device__ __forceinline__ void sts4(uint32_t dst, float4 v) {
    asm volatile("st.shared.v4.f32 [%0], {%1, %2, %3, %4};"
                 :: "r"(dst), "f"(v.x), "f"(v.y), "f"(v.z), "f"(v.w) : "memory");
}
__device__ __forceinline__ void sts4u(uint32_t dst, uint4 v) {
    asm volatile("st.shared.v4.u32 [%0], {%1, %2, %3, %4};"
                 :: "r"(dst), "r"(v.x), "r"(v.y), "r"(v.z), "r"(v.w) : "memory");
}
__device__ __forceinline__ uint32_t pack2(float a, float b) {
    __half2 h = __floats2half2_rn(a, b);
    return *reinterpret_cast<uint32_t*>(&h);
}

#if TC_AVAIL
__device__ __forceinline__ uint64_t mk_desc(uint32_t addr) {
    // SW128, version=1 (Blackwell), LBO=1, SBO=64 (K-major)
    const uint64_t BASE = (2ULL << 61) | (1ULL << 46) | (64ULL << 32) | (1ULL << 16);
    return BASE | ((uint64_t)(addr >> 4) & 0x3FFF);
}

// tf32: acc=F32, atype=btype=TF32(2), N=128, M=128
#define IDESC_TF32 ((1u << 4) | (2u << 7) | (2u << 10) | (16u << 17) | (8u << 24))
// fp16: acc=F32, atype=btype=FP16(0), N=128, M=128
#define IDESC_F16  ((1u << 4) | (16u << 17) | (8u << 24))

__device__ __forceinline__ void mma_tf32_ss(uint32_t d, uint64_t a, uint64_t b,
                                            uint32_t en) {
    asm volatile(
        "{\n\t.reg .pred p;\n\t"
        "setp.ne.u32 p, %4, 0;\n\t"
        "tcgen05.mma.cta_group::1.kind::tf32 [%0], %1, %2, %3, p;\n\t}"
        :: "r"(d), "l"(a), "l"(b), "r"(IDESC_TF32), "r"(en) : "memory");
}
__device__ __forceinline__ void mma_f16_ss(uint32_t d, uint64_t a, uint64_t b,
                                           uint32_t en) {
    asm volatile(
        "{\n\t.reg .pred p;\n\t"
        "setp.ne.u32 p, %4, 0;\n\t"
        "tcgen05.mma.cta_group::1.kind::f16 [%0], %1, %2, %3, p;\n\t}"
        :: "r"(d), "l"(a), "l"(b), "r"(IDESC_F16), "r"(en) : "memory");
}
// TS-mode: A operand in TMEM (fp16x2 columns), B in SMEM.
__device__ __forceinline__ void mma_f16_ts(uint32_t d, uint32_t a, uint64_t b,
                                           uint32_t en) {
    asm volatile(
        "{\n\t.reg .pred p;\n\t"
        "setp.ne.u32 p, %4, 0;\n\t"
        "tcgen05.mma.cta_group::1.kind::f16 [%0], [%1], %2, %3, p;\n\t}"
        :: "r"(d), "r"(a), "l"(b), "r"(IDESC_F16), "r"(en) : "memory");
}

__device__ __forceinline__ void tc_commit(uint32_t mbar) {
    asm volatile(
        "tcgen05.commit.cta_group::1.mbarrier::arrive::one.shared::cluster.b64 [%0];"
        :: "r"(mbar) : "memory");
}

#define TC_LD_X32(r, addr)                                                     \
    asm volatile(                                                              \
        "tcgen05.ld.sync.aligned.32x32b.x32.b32 "                              \
        "{%0, %1, %2, %3, %4, %5, %6, %7, "                                    \
        " %8, %9, %10, %11, %12, %13, %14, %15, "                              \
        " %16, %17, %18, %19, %20, %21, %22, %23, "                            \
        " %24, %25, %26, %27, %28, %29, %30, %31}, [%32];"                     \
        : "=r"((r)[0]),  "=r"((r)[1]),  "=r"((r)[2]),  "=r"((r)[3]),           \
          "=r"((r)[4]),  "=r"((r)[5]),  "=r"((r)[6]),  "=r"((r)[7]),           \
          "=r"((r)[8]),  "=r"((r)[9]),  "=r"((r)[10]), "=r"((r)[11]),          \
          "=r"((r)[12]), "=r"((r)[13]), "=r"((r)[14]), "=r"((r)[15]),          \
          "=r"((r)[16]), "=r"((r)[17]), "=r"((r)[18]), "=r"((r)[19]),          \
          "=r"((r)[20]), "=r"((r)[21]), "=r"((r)[22]), "=r"((r)[23]),          \
          "=r"((r)[24]), "=r"((r)[25]), "=r"((r)[26]), "=r"((r)[27]),          \
          "=r"((r)[28]), "=r"((r)[29]), "=r"((r)[30]), "=r"((r)[31])           \
        : "r"(addr))

#define TC_ST_X32(addr, r)                                                     \
    asm volatile(                                                              \
        "tcgen05.st.sync.aligned.32x32b.x32.b32 [%0], "                        \
        "{%1, %2, %3, %4, %5, %6, %7, %8, "                                    \
        " %9, %10, %11, %12, %13, %14, %15, %16, "                             \
        " %17, %18, %19, %20, %21, %22, %23, %24, "                            \
        " %25, %26, %27, %28, %29, %30, %31, %32};"                            \
        :: "r"(addr),                                                          \
           "r"((r)[0]),  "r"((r)[1]),  "r"((r)[2]),  "r"((r)[3]),              \
           "r"((r)[4]),  "r"((r)[5]),  "r"((r)[6]),  "r"((r)[7]),              \
           "r"((r)[8]),  "r"((r)[9]),  "r"((r)[10]), "r"((r)[11]),             \
           "r"((r)[12]), "r"((r)[13]), "r"((r)[14]), "r"((r)[15]),             \
           "r"((r)[16]), "r"((r)[17]), "r"((r)[18]), "r"((r)[19]),             \
           "r"((r)[20]), "r"((r)[21]), "r"((r)[22]), "r"((r)[23]),             \
           "r"((r)[24]), "r"((r)[25]), "r"((r)[26]), "r"((r)[27]),             \
           "r"((r)[28]), "r"((r)[29]), "r"((r)[30]), "r"((r)[31])              \
        : "memory")
#endif  // TC_AVAIL

__device__ __forceinline__ void mbar_init(uint32_t a, uint32_t cnt) {
    asm volatile("mbarrier.init.shared.b64 [%0], %1;" :: "r"(a), "r"(cnt) : "memory");
}
__device__ __forceinline__ void mbar_wait(uint32_t a, uint32_t parity) {
    asm volatile(
        "{\n\t.reg .pred P;\n"
        "WL%=:\n\t"
        "mbarrier.try_wait.parity.acquire.cta.shared::cta.b64 P, [%0], %1, 0x989680;\n\t"
        "@P bra WD%=;\n\t"
        "bra WL%=;\n"
        "WD%=:\n\t}"
        :: "r"(a), "r"(parity) : "memory");
}

// ---------------------------------------------------------------------------
// k_prep (unchanged)
// ---------------------------------------------------------------------------
__global__ void k_prep(const float* __restrict__ W_in,
                       const float* __restrict__ msg_W,
                       const float* __restrict__ upd_W,
                       const float* __restrict__ W_out,
                       const float* __restrict__ Ws1,
                       const float* __restrict__ Wh1,
                       const float* __restrict__ bs1,
                       const float* __restrict__ bh1,
                       const float* __restrict__ b_out,
                       float* __restrict__ wt,
                       __half* __restrict__ wth,
                       int* __restrict__ off,
                       float* __restrict__ logdet) {
    const int TOTAL = 12544 + 147456 + (BN_ + 1) + 32;
    for (int idx = blockIdx.x * blockDim.x + threadIdx.x; idx < TOTAL;
         idx += gridDim.x * blockDim.x) {
        if (idx < 12288) {
            int n = idx / 96, k = idx - n * 96;
            wt[idx] = (k < 67) ? W_in[k * 128 + n] : 0.f;
        } else if (idx < 12416) {
            int n = idx - 12288;
            float v = bs1[n];
            for (int q = 0; q < 128; q++)
                v = fmaf(b_out[q], Ws1[q * 128 + n], v);
            wt[idx] = v;
        } else if (idx < 12544) {
            int n = idx - 12416;
            float v = bh1[n];
            for (int q = 0; q < 128; q++)
                v = fmaf(b_out[q], Wh1[q * 128 + n], v);
            wt[idx] = v;
        } else {
            int j = idx - 12544;
            if (j < 32768) {
                int l = j >> 14, r = j & 16383;
                int n = r >> 7, k = r & 127;
                wth[j] = __float2half(msg_W[l * 16384 + k * 128 + n]);
            } else if (j < 98304) {
                int j2 = j - 32768;
                int l = j2 >> 15, r = j2 & 32767;
                int n = r >> 8, k = r & 255;
                wth[j] = __float2half(upd_W[l * 32768 + k * 128 + n]);
            } else if (j < 122880) {
                int j2 = j - 98304;
                int n = j2 / 192, k = j2 - n * 192;
                float v = 0.f;
                if (k < 128) {
                    for (int q = 0; q < 128; q++)
                        v = fmaf(W_out[k * 128 + q], Ws1[q * 128 + n], v);
                } else if (k < 131) {
                    v = Ws1[k * 128 + n];
                }
                wth[j] = __float2half(v);
            } else if (j < 147456) {
                int j2 = j - 122880;
                int n = j2 / 192, k = j2 - n * 192;
                float v = 0.f;
                if (k < 128) {
                    for (int q = 0; q < 128; q++)
                        v = fmaf(W_out[k * 128 + q], Wh1[q * 128 + n], v);
                } else if (k < 131) {
                    v = Wh1[k * 128 + n];
                }
                wth[j] = __float2half(v);
            } else if (j < 147456 + BN_ + 1) {
                off[j - 147456] = 0;
            } else {
                logdet[j - (147456 + BN_ + 1)] = 0.f;
            }
        }
    }
}

// ---------------------------------------------------------------------------
// CSR build (unchanged)
// ---------------------------------------------------------------------------
__global__ void k_hist(const int* __restrict__ adj, const int* __restrict__ ebi,
                       int* __restrict__ deg) {
    int e = blockIdx.x * blockDim.x + threadIdx.x;
    if (e >= E_) return;
    int dst = ebi[e] * N_ + adj[2 * e + 1];
    atomicAdd(&deg[dst], 1);
}

__global__ void k_scanA(int* __restrict__ off, int* __restrict__ part) {
    __shared__ int s[512];
    int t = threadIdx.x;
    int i = blockIdx.x * 512 + t;
    int v = off[i];
    s[t] = v; __syncthreads();
    for (int d = 1; d < 512; d <<= 1) {
        int x = (t >= d) ? s[t - d] : 0;
        __syncthreads();
        s[t] += x;
        __syncthreads();
    }
    off[i] = s[t] - v;
    if (t == 511) part[blockIdx.x] = s[t];
}

__global__ void k_scanB(int* __restrict__ off, const int* __restrict__ part,
                        int* __restrict__ cur) {
    __shared__ int s[512];
    int t = threadIdx.x, b = blockIdx.x;
    s[t] = part[t]; __syncthreads();
    for (int d = 1; d < 512; d <<= 1) {
        int x = (t >= d) ? s[t - d] : 0;
        __syncthreads();
        s[t] += x;
        __syncthreads();
    }
    int prefix = (b == 0) ? 0 : s[b - 1];
    int i = b * 512 + t;
    int v = off[i] + prefix;
    off[i] = v;
    cur[i] = v;
    if (b == 0 && t == 0) off[BN_] = E_;
}

__global__ void k_place(const int* __restrict__ adj, const int* __restrict__ ebi,
                        int* __restrict__ cur, int* __restrict__ srcl) {
    int e = blockIdx.x * blockDim.x + threadIdx.x;
    if (e >= E_) return;
    int b = ebi[e];
    int src = b * N_ + adj[2 * e];
    int dst = b * N_ + adj[2 * e + 1];
    int pos = atomicAdd(&cur[dst], 1);
    srcl[pos] = src;
}

// ---------------------------------------------------------------------------
// Gather (unchanged): half-warp per node, uint4 lanes, 4-way unroll.
// ---------------------------------------------------------------------------
__global__ void k_gather(const __half* __restrict__ msg,
                         const int* __restrict__ off,
                         const int* __restrict__ srcl,
                         __half* __restrict__ agg) {
    int gwarp = (blockIdx.x * blockDim.x + threadIdx.x) >> 5;
    int lane  = threadIdx.x & 31;
    int half_ = lane >> 4;
    int l16   = lane & 15;
    int node  = gwarp * 2 + half_;
    int s0 = off[node], s1 = off[node + 1];

    float a[8] = {0.f, 0.f, 0.f, 0.f, 0.f, 0.f, 0.f, 0.f};
    int j = s0;
    for (; j + 4 <= s1; j += 4) {
        uint4 v0 = *((const uint4*)(msg + (size_t)srcl[j]     * 128) + l16);
        uint4 v1 = *((const uint4*)(msg + (size_t)srcl[j + 1] * 128) + l16);
        uint4 v2 = *((const uint4*)(msg + (size_t)srcl[j + 2] * 128) + l16);
        uint4 v3 = *((const uint4*)(msg + (size_t)srcl[j + 3] * 128) + l16);
        const uint32_t* ws[4] = {&v0.x, &v1.x, &v2.x, &v3.x};
#pragma unroll
        for (int e = 0; e < 4; e++)
#pragma unroll
            for (int q = 0; q < 4; q++) {
                float2 f = __half22float2(*(const __half2*)&ws[e][q]);
                a[q * 2] += f.x; a[q * 2 + 1] += f.y;
            }
    }
    for (; j < s1; j++) {
        uint4 v = *((const uint4*)(msg + (size_t)srcl[j] * 128) + l16);
        const uint32_t* w = &v.x;
#pragma unroll
        for (int q = 0; q < 4; q++) {
            float2 f = __half22float2(*(const __half2*)&w[q]);
            a[q * 2] += f.x; a[q * 2 + 1] += f.y;
        }
    }
    uint4 o;
    o.x = pack2(a[0], a[1]); o.y = pack2(a[2], a[3]);
    o.z = pack2(a[4], a[5]); o.w = pack2(a[6], a[7]);
    *((uint4*)(agg + (size_t)node * 128) + l16) = o;
}

// ===========================================================================
// FUSED in/upd kernels, M=256 per CTA (unchanged from R16, passing).
// ===========================================================================
#define RING_OFF     1024
#define STG          49152
#define SMEM_FUSED   (1024 + 2 * STG)     // 99328

#if TC_AVAIL
__device__ __forceinline__ void stage_msgW(uint32_t sb, int tid,
                                           const __half* msgW, uint32_t dsto) {
#pragma unroll
    for (int it = 0; it < 8; it++) {
        int idx = tid + it * 256;
        int chunk = idx >> 10, w = idx & 1023;
        int r = w >> 3, c4 = w & 7;
        uint32_t dst = sb + RING_OFF + dsto + chunk * 16384
                     + SW128((uint32_t)(r * 128 + c4 * 16));
        cp16(dst, msgW + (size_t)r * 128 + chunk * 64 + c4 * 8);
    }
    cp_commit();
}

__device__ __forceinline__ void epi1_256(uint32_t sb, uint32_t tmem,
                                         int wid, int lid, int block_row,
                                         const float* bias,
                                         const unsigned char* maskB,
                                         __half* Ch, const uint32_t* hofs) {
    const int tile = wid >> 2;
    const int sp   = wid & 3;
    const int row  = sp * 32 + lid;
    const int m    = block_row + tile * 128 + row;
    const bool masked = (maskB[m] != 0);
    const uint32_t tb = tmem + tile * 128;
#pragma unroll
    for (int half = 0; half < 2; half++) {
        int cb = half * 64;
#pragma unroll
        for (int q = 0; q < 2; q++) {
            int c0 = cb + q * 32;
            uint32_t r32[32];
            TC_LD_X32(r32, tb + c0);
            asm volatile("tcgen05.wait::ld.sync.aligned;" ::: "memory");
#pragma unroll
            for (int j = 0; j < 32; j += 8) {
                float f[8];
#pragma unroll
                for (int i = 0; i < 8; i++) {
                    float v = __uint_as_float(r32[j + i]) + bias[c0 + j + i];
                    v = fmaxf(v, 0.f);
                    if (masked) v = 0.f;
                    f[i] = v;
                }
                uint4 o;
                o.x = pack2(f[0], f[1]); o.y = pack2(f[2], f[3]);
                o.z = pack2(f[4], f[5]); o.w = pack2(f[6], f[7]);
                *(uint4*)(Ch + (size_t)m * 128 + c0 + j) = o;
                uint32_t boff = (uint32_t)(((c0 & 63) + j) * 2);
                sts4u(sb + RING_OFF + hofs[tile * 2 + half]
                      + SW128((uint32_t)(row * 128) + boff), o);
            }
        }
    }
    asm volatile("tcgen05.fence::before_thread_sync;" ::: "memory");
}

__device__ __forceinline__ void phase2_256(uint32_t sb, uint32_t tmem,
                                           int tid, int wid, int lid,
                                           int block_row, const float* bias2,
                                           __half* Cm, const uint32_t* hofs,
                                           uint32_t woff) {
    cp_wait0();
    __syncthreads();
    if (tid == 0) {
        asm volatile("tcgen05.fence::after_thread_sync;" ::: "memory");
        asm volatile("fence.proxy.async.shared::cta;" ::: "memory");
#pragma unroll
        for (int tile = 0; tile < 2; tile++) {
#pragma unroll
            for (int c = 0; c < 2; c++) {
                uint64_t hd = mk_desc(sb + RING_OFF + hofs[tile * 2 + c]);
                uint64_t wd = mk_desc(sb + RING_OFF + woff + c * 16384);
#pragma unroll
                for (int j = 0; j < 4; j++)
                    mma_f16_ss(tmem + tile * 128, hd + j * 2, wd + j * 2,
                               (c > 0 || j > 0) ? 1u : 0u);
            }
        }
        tc_commit(sb + 24);
    }
    mbar_wait(sb + 24, 0);
    asm volatile("tcgen05.fence::after_thread_sync;" ::: "memory");

    const int tile = wid >> 2;
    const int sp   = wid & 3;
    const int m    = block_row + tile * 128 + sp * 32 + lid;
    const uint32_t tb = tmem + tile * 128;
#pragma unroll
    for (int cb = 0; cb < 128; cb += 32) {
        uint32_t r32[32];
        TC_LD_X32(r32, tb + cb);
        asm volatile("tcgen05.wait::ld.sync.aligned;" ::: "memory");
#pragma unroll
        for (int j = 0; j < 32; j += 8) {
            float f[8];
#pragma unroll
            for (int i = 0; i < 8; i++)
                f[i] = fmaxf(__uint_as_float(r32[j + i]) + bias2[cb + j + i], 0.f);
            uint4 o;
            o.x = pack2(f[0], f[1]); o.y = pack2(f[2], f[3]);
            o.z = pack2(f[4], f[5]); o.w = pack2(f[6], f[7]);
            *(uint4*)(Cm + (size_t)m * 128 + cb + j) = o;
        }
    }
}
#endif  // TC_AVAIL

// ----- fused input layer (tf32 phase1, K=67 pad 96, M=256) + msg0 -----
struct FIN {
    const float* emb; const int* types; const float* coords;
    const float* Wt; const float* bias;
    const unsigned char* maskB;
    __half* Ch;
    const __half* msgW; const float* bias2; __half* Cm;
};

__global__ void __launch_bounds__(256) k_fused_in(FIN g) {
#if TC_AVAIL
    extern __shared__ __align__(1024) char smem[];
    const uint32_t sb = smem_u32(smem);
    const int tid = threadIdx.x;
    const int wid = tid >> 5;
    const int lid = tid & 31;
    const int block_row = blockIdx.x * 256;

    auto stage1 = [&](int t, int s) {
        uint32_t bufA = sb + RING_OFF + s * STG;
        uint32_t bufW = bufA + 32768;
#pragma unroll
        for (int it = 0; it < 4; it++) {
            int idx = tid + it * 256;
            int r = idx >> 3, c4 = idx & 7;
            cp16(bufW + SW128((uint32_t)(r * 128 + c4 * 16)),
                 g.Wt + (size_t)r * 96 + t * 32 + c4 * 4);
        }
#pragma unroll
        for (int it = 0; it < 8; it++) {
            int idx = tid + it * 256;
            int r = idx >> 3, c4 = idx & 7;
            int gr = block_row + r;
            uint32_t dst = bufA + SW128((uint32_t)(r * 128 + c4 * 16));
            if (t < 2) {
                cp16(dst, g.emb + (size_t)g.types[gr] * 64 + t * 32 + c4 * 4);
            } else {
                float4 v = make_float4(0.f, 0.f, 0.f, 0.f);
                if (c4 == 0) {
                    v.x = g.coords[gr * 3];
                    v.y = g.coords[gr * 3 + 1];
                    v.z = g.coords[gr * 3 + 2];
                }
                sts4(dst, v);
            }
        }
        cp_commit();
    };

    stage1(0, 0);
    stage1(1, 1);
    if (wid == 0) {
        asm volatile(
            "tcgen05.alloc.cta_group::1.sync.aligned.shared::cta.b32 [%0], %1;"
            :: "r"(sb), "r"(256u) : "memory");
        asm volatile("tcgen05.relinquish_alloc_permit.cta_group::1.sync.aligned;");
    }
    if (tid == 0) {
        mbar_init(sb + 8, 1); mbar_init(sb + 16, 1); mbar_init(sb + 24, 1);
    }
    __syncthreads();
    uint32_t tmem;
    asm volatile("ld.shared.b32 %0, [%1];" : "=r"(tmem) : "r"(sb));

    uint64_t d0A0 = mk_desc(sb + RING_OFF);
    uint64_t d0A1 = mk_desc(sb + RING_OFF + 16384);
    uint64_t d0W  = mk_desc(sb + RING_OFF + 32768);
    uint64_t d1A0 = mk_desc(sb + RING_OFF + STG);
    uint64_t d1A1 = mk_desc(sb + RING_OFF + STG + 16384);
    uint64_t d1W  = mk_desc(sb + RING_OFF + STG + 32768);

    cp_wait1(); __syncthreads();
    if (tid == 0) {
        asm volatile("fence.proxy.async.shared::cta;" ::: "memory");
#pragma unroll
        for (int j = 0; j < 4; j++) {
            uint32_t en = (j > 0) ? 1u : 0u;
            mma_tf32_ss(tmem,       d0A0 + j * 2, d0W + j * 2, en);
            mma_tf32_ss(tmem + 128, d0A1 + j * 2, d0W + j * 2, en);
        }
        tc_commit(sb + 8);
    }
    mbar_wait(sb + 8, 0);
    stage1(2, 0);

    cp_wait1(); __syncthreads();
    if (tid == 0) {
        asm volatile("fence.proxy.async.shared::cta;" ::: "memory");
#pragma unroll
        for (int j = 0; j < 4; j++) {
            mma_tf32_ss(tmem,       d1A0 + j * 2, d1W + j * 2, 1u);
            mma_tf32_ss(tmem + 128, d1A1 + j * 2, d1W + j * 2, 1u);
        }
        tc_commit(sb + 16);
    }
    mbar_wait(sb + 16, 0);
    stage_msgW(sb, tid, g.msgW, STG);

    cp_wait1(); __syncthreads();
    if (tid == 0) {
        asm volatile("fence.proxy.async.shared::cta;" ::: "memory");
#pragma unroll
        for (int j = 0; j < 4; j++) {
            mma_tf32_ss(tmem,       d0A0 + j * 2, d0W + j * 2, 1u);
            mma_tf32_ss(tmem + 128, d0A1 + j * 2, d0W + j * 2, 1u);
        }
        tc_commit(sb + 8);
    }
    mbar_wait(sb + 8, 1);
    asm volatile("tcgen05.fence::after_thread_sync;" ::: "memory");

    const uint32_t hofs[4] = {0u, 16384u, 32768u, 81920u};
    epi1_256(sb, tmem, wid, lid, block_row, g.bias, g.maskB, g.Ch, hofs);
    phase2_256(sb, tmem, tid, wid, lid, block_row, g.bias2, g.Cm, hofs, STG);

    __syncthreads();
    if (wid == 0) {
        asm volatile("tcgen05.dealloc.cta_group::1.sync.aligned.b32 %0, %1;"
                     :: "r"(tmem), "r"(256u));
    }
#else
    const int m = blockIdx.x * 256 + threadIdx.x;
    const bool masked = (g.maskB[m] != 0);
    int ty = g.types[m];
    for (int cb = 0; cb < 128; cb++) {
        float acc = 0.f;
        for (int k = 0; k < 64; k++)
            acc = fmaf(g.emb[(size_t)ty * 64 + k], g.Wt[(size_t)cb * 96 + k], acc);
        for (int k = 64; k < 67; k++)
            acc = fmaf(g.coords[m * 3 + (k - 64)], g.Wt[(size_t)cb * 96 + k], acc);
        float v = fmaxf(acc + g.bias[cb], 0.f);
        if (masked) v = 0.f;
        g.Ch[(size_t)m * 128 + cb] = __float2half(v);
    }
    for (int cb = 0; cb < 128; cb++) {
        float acc = 0.f;
        for (int k = 0; k < 128; k++)
            acc = fmaf(__half2float(g.Ch[(size_t)m * 128 + k]),
                       __half2float(g.msgW[(size_t)cb * 128 + k]), acc);
        g.Cm[(size_t)m * 128 + cb] = __float2half(fmaxf(acc + g.bias2[cb], 0.f));
    }
#endif
}

// ----- fused upd layer (f16 phase1, K=256 concat [h|agg], M=256) + msg -----
struct FUP {
    const __half* A1; const __half* A2;
    const __half* Wt; const float* bias;
    const unsigned char* maskB;
    __half* Ch;
    const __half* msgW; const float* bias2; __half* Cm;
};

__global__ void __launch_bounds__(256) k_fused_upd(FUP g) {
#if TC_AVAIL
    extern __shared__ __align__(1024) char smem[];
    const uint32_t sb = smem_u32(smem);
    const int tid = threadIdx.x;
    const int wid = tid >> 5;
    const int lid = tid & 31;
    const int block_row = blockIdx.x * 256;

    auto stage1 = [&](int t, int s) {
        uint32_t bufA = sb + RING_OFF + s * STG;
        uint32_t bufW = bufA + 32768;
#pragma unroll
        for (int it = 0; it < 4; it++) {
            int idx = tid + it * 256;
            int r = idx >> 3, c4 = idx & 7;
            cp16(bufW + SW128((uint32_t)(r * 128 + c4 * 16)),
                 g.Wt + (size_t)r * 256 + t * 64 + c4 * 8);
        }
#pragma unroll
        for (int it = 0; it < 8; it++) {
            int idx = tid + it * 256;
            int r = idx >> 3, c4 = idx & 7;
            int gr = block_row + r;
            const __half* src = (t < 2)
                ? g.A1 + (size_t)gr * 128 + t * 64 + c4 * 8
                : g.A2 + (size_t)gr * 128 + (t - 2) * 64 + c4 * 8;
            cp16(bufA + SW128((uint32_t)(r * 128 + c4 * 16)), src);
        }
        cp_commit();
    };

    stage1(0, 0);
    stage1(1, 1);
    if (wid == 0) {
        asm volatile(
            "tcgen05.alloc.cta_group::1.sync.aligned.shared::cta.b32 [%0], %1;"
            :: "r"(sb), "r"(256u) : "memory");
        asm volatile("tcgen05.relinquish_alloc_permit.cta_group::1.sync.aligned;");
    }
    if (tid == 0) {
        mbar_init(sb + 8, 1); mbar_init(sb + 16, 1); mbar_init(sb + 24, 1);
    }
    __syncthreads();
    uint32_t tmem;
    asm volatile("ld.shared.b32 %0, [%1];" : "=r"(tmem) : "r"(sb));

    uint64_t d0A0 = mk_desc(sb + RING_OFF);
    uint64_t d0A1 = mk_desc(sb + RING_OFF + 16384);
    uint64_t d0W  = mk_desc(sb + RING_OFF + 32768);
    uint64_t d1A0 = mk_desc(sb + RING_OFF + STG);
    uint64_t d1A1 = mk_desc(sb + RING_OFF + STG + 16384);
    uint64_t d1W  = mk_desc(sb + RING_OFF + STG + 32768);

    cp_wait1(); __syncthreads();
    if (tid == 0) {
        asm volatile("fence.proxy.async.shared::cta;" ::: "memory");
#pragma unroll
        for (int j = 0; j < 4; j++) {
            uint32_t en = (j > 0) ? 1u : 0u;
            mma_f16_ss(tmem,       d0A0 + j * 2, d0W + j * 2, en);
            mma_f16_ss(tmem + 128, d0A1 + j * 2, d0W + j * 2, en);
        }
        tc_commit(sb + 8);
    }
    mbar_wait(sb + 8, 0);
    stage1(2, 0);

    cp_wait1(); __syncthreads();
    if (tid == 0) {
        asm volatile("fence.proxy.async.shared::cta;" ::: "memory");
#pragma unroll
        for (int j = 0; j < 4; j++) {
            mma_f16_ss(tmem,       d1A0 + j * 2, d1W + j * 2, 1u);
            mma_f16_ss(tmem + 128, d1A1 + j * 2, d1W + j * 2, 1u);
        }
        tc_commit(sb + 16);
    }
    mbar_wait(sb + 16, 0);
    stage1(3, 1);

    cp_wait1(); __syncthreads();
    if (tid == 0) {
        asm volatile("fence.proxy.async.shared::cta;" ::: "memory");
#pragma unroll
        for (int j = 0; j < 4; j++) {
            mma_f16_ss(tmem,       d0A0 + j * 2, d0W + j * 2, 1u);
            mma_f16_ss(tmem + 128, d0A1 + j * 2, d0W + j * 2, 1u);
        }
        tc_commit(sb + 8);
    }
    mbar_wait(sb + 8, 1);
    stage_msgW(sb, tid, g.msgW, 0);

    cp_wait1(); __syncthreads();
    if (tid == 0) {
        asm volatile("fence.proxy.async.shared::cta;" ::: "memory");
#pragma unroll
        for (int j = 0; j < 4; j++) {
            mma_f16_ss(tmem,       d1A0 + j * 2, d1W + j * 2, 1u);
            mma_f16_ss(tmem + 128, d1A1 + j * 2, d1W + j * 2, 1u);
        }
        tc_commit(sb + 16);
    }
    mbar_wait(sb + 16, 1);
    asm volatile("tcgen05.fence::after_thread_sync;" ::: "memory");

    const uint32_t hofs[4] = {32768u, 49152u, 65536u, 81920u};
    epi1_256(sb, tmem, wid, lid, block_row, g.bias, g.maskB, g.Ch, hofs);
    phase2_256(sb, tmem, tid, wid, lid, block_row, g.bias2, g.Cm, hofs, 0);

    __syncthreads();
    if (wid == 0) {
        asm volatile("tcgen05.dealloc.cta_group::1.sync.aligned.b32 %0, %1;"
                     :: "r"(tmem), "r"(256u));
    }
#else
    const int m = blockIdx.x * 256 + threadIdx.x;
    const bool masked = (g.maskB[m] != 0);
    for (int cb = 0; cb < 128; cb++) {
        float acc = 0.f;
        for (int k = 0; k < 128; k++)
            acc = fmaf(__half2float(g.A1[(size_t)m * 128 + k]),
                       __half2float(g.Wt[(size_t)cb * 256 + k]), acc);
        for (int k = 0; k < 128; k++)
            acc = fmaf(__half2float(g.A2[(size_t)m * 128 + k]),
                       __half2float(g.Wt[(size_t)cb * 256 + 128 + k]), acc);
        float v = fmaxf(acc + g.bias[cb], 0.f);
        if (masked) v = 0.f;
        g.Ch[(size_t)m * 128 + cb] = __float2half(v);
    }
    for (int cb = 0; cb < 128; cb++) {
        float acc = 0.f;
        for (int k = 0; k < 128; k++)
            acc = fmaf(__half2float(g.Ch[(size_t)m * 128 + k]),
                       __half2float(g.msgW[(size_t)cb * 128 + k]), acc);
        g.Cm[(size_t)m * 128 + cb] = __float2half(fmaxf(acc + g.bias2[cb], 0.f));
    }
#endif
}

// ===========================================================================
// k_fused_tail: upd1 + coupling (unchanged from R15/R16, passing).
// ===========================================================================
#define TAIL_HDR   8192
#define SMEM_TAIL  (TAIL_HDR + 65536)
struct FT {
    const __half* A1; const __half* A2;
    const __half* Wt; const float* bias;
    const __half* Wse; const __half* Whe;
    const float* bse; const float* bhe;
    const float* Ws2; const float* bs2;
    const float* Wh2; const float* bh2;
    const float* coords;
    const unsigned char* maskB;
    float* out; float* logdet;
};

__global__ void __launch_bounds__(256) k_fused_tail(FT g) {
#if TC_AVAIL
    extern __shared__ __align__(1024) char smem[];
    const uint32_t sb = smem_u32(smem);
    float* smf = (float*)smem;
    const int tid = threadIdx.x;
    const int wid = tid >> 5;
    const int lid = tid & 31;
    const int block_row = blockIdx.x * 128;

    auto stage1 = [&](int t, int s) {
        uint32_t bufA = sb + TAIL_HDR + s * 32768;
        uint32_t bufW = bufA + 16384;
#pragma unroll
        for (int it = 0; it < 4; it++) {
            int idx = tid + it * 256;
            int r = idx >> 3, c4 = idx & 7;
            cp16(bufW + SW128((uint32_t)(r * 128 + c4 * 16)),
                 g.Wt + (size_t)r * 256 + t * 64 + c4 * 8);
        }
#pragma unroll
        for (int it = 0; it < 4; it++) {
            int idx = tid + it * 256;
            int r = idx >> 3, c4 = idx & 7;
            int gr = block_row + r;
            const __half* src = (t < 2)
                ? g.A1 + (size_t)gr * 128 + t * 64 + c4 * 8
                : g.A2 + (size_t)gr * 128 + (t - 2) * 64 + c4 * 8;
            cp16(bufA + SW128((uint32_t)(r * 128 + c4 * 16)), src);
        }
        cp_commit();
    };
    auto stageCW = [&](const __half* W, int s) {
        uint32_t base = sb + TAIL_HDR + s * 32768;
#pragma unroll
        for (int it = 0; it < 8; it++) {
            int idx = tid + it * 256;
            int chunk = idx >> 10, w = idx & 1023;
            int r = w >> 3, c4 = w & 7;
            cp16(base + chunk * 16384 + SW128((uint32_t)(r * 128 + c4 * 16)),
                 W + (size_t)r * 192 + chunk * 64 + c4 * 8);
        }
        cp_commit();
    };

    stage1(0, 0);
    stage1(1, 1);
    if (wid == 0) {
        asm volatile(
            "tcgen05.alloc.cta_group::1.sync.aligned.shared::cta.b32 [%0], %1;"
            :: "r"(sb), "r"(256u) : "memory");
        asm volatile("tcgen05.relinquish_alloc_permit.cta_group::1.sync.aligned;");
    }
    if (tid == 0) {
        mbar_init(sb + 8, 1); mbar_init(sb + 16, 1); mbar_init(sb + 24, 1);
    }
    for (int i = tid; i < 384; i += 256) {
        smf[16 + i]   = g.Ws2[i];
        smf[400 + i]  = g.Wh2[i];
        int n = i / 3, c = i - n * 3;
        smf[1040 + i] = __half2float(g.Wse[(size_t)n * 192 + 128 + c]);
        smf[1424 + i] = __half2float(g.Whe[(size_t)n * 192 + 128 + c]);
    }
    if (tid < 128) {
        smf[784 + tid] = g.bse[tid];
        smf[912 + tid] = g.bhe[tid];
    }
    __syncthreads();
    uint32_t tmem;
    asm volatile("ld.shared.b32 %0, [%1];" : "=r"(tmem) : "r"(sb));

    uint64_t d0A = mk_desc(sb + TAIL_HDR);
    uint64_t d0W = mk_desc(sb + TAIL_HDR + 16384);
    uint64_t d1A = mk_desc(sb + TAIL_HDR + 32768);
    uint64_t d1W = mk_desc(sb + TAIL_HDR + 49152);

    cp_wait1(); __syncthreads();
    if (tid == 0) {
        asm volatile("fence.proxy.async.shared::cta;" ::: "memory");
#pragma unroll
        for (int j = 0; j < 4; j++)
            mma_f16_ss(tmem, d0A + j * 2, d0W + j * 2, (j > 0) ? 1u : 0u);
        tc_commit(sb + 8);
    }
    mbar_wait(sb + 8, 0);
    stage1(2, 0);

    cp_wait1(); __syncthreads();
    if (tid == 0) {
        asm volatile("fence.proxy.async.shared::cta;" ::: "memory");
#pragma unroll
        for (int j = 0; j < 4; j++)
            mma_f16_ss(tmem, d1A + j * 2, d1W + j * 2, 1u);
        tc_commit(sb + 16);
    }
    mbar_wait(sb + 16, 0);
    stage1(3, 1);

    cp_wait1(); __syncthreads();
    if (tid == 0) {
        asm volatile("fence.proxy.async.shared::cta;" ::: "memory");
#pragma unroll
        for (int j = 0; j < 4; j++)
            mma_f16_ss(tmem, d0A + j * 2, d0W + j * 2, 1u);
        tc_commit(sb + 8);
    }
    mbar_wait(sb + 8, 1);
    stageCW(g.Wse, 0);

    cp_wait1(); __syncthreads();
    if (tid == 0) {
        asm volatile("fence.proxy.async.shared::cta;" ::: "memory");
#pragma unroll
        for (int j = 0; j < 4; j++)
            mma_f16_ss(tmem, d1A + j * 2, d1W + j * 2, 1u);
        tc_commit(sb + 16);
    }
    mbar_wait(sb + 16, 1);
    stageCW(g.Whe, 1);
    asm volatile("tcgen05.fence::after_thread_sync;" ::: "memory");

    const int m = block_row + (wid & 3) * 32 + lid;
    if (wid < 4) {
        const bool masked = (g.maskB[m] != 0);
        uint32_t a2[64];
#pragma unroll
        for (int cb = 0; cb < 128; cb += 32) {
            uint32_t r32[32];
            TC_LD_X32(r32, tmem + cb);
            asm volatile("tcgen05.wait::ld.sync.aligned;" ::: "memory");
#pragma unroll
            for (int j = 0; j < 32; j += 2) {
                float v0 = fmaxf(__uint_as_float(r32[j])     + g.bias[cb + j],     0.f);
                float v1 = fmaxf(__uint_as_float(r32[j + 1]) + g.bias[cb + j + 1], 0.f);
                if (masked) { v0 = 0.f; v1 = 0.f; }
                a2[(cb + j) >> 1] = pack2(v0, v1);
            }
        }
        uint32_t woff = (uint32_t)wid << 21;
        TC_ST_X32(tmem + 128 + woff, a2);
        TC_ST_X32(tmem + 160 + woff, a2 + 32);
        asm volatile("tcgen05.wait::st.sync.aligned;" ::: "memory");
    }
    asm volatile("tcgen05.fence::before_thread_sync;" ::: "memory");

    cp_wait1();
    __syncthreads();
    if (tid == 0) {
        asm volatile("tcgen05.fence::after_thread_sync;" ::: "memory");
        asm volatile("fence.proxy.async.shared::cta;" ::: "memory");
#pragma unroll
        for (int c = 0; c < 2; c++) {
            uint64_t wd = mk_desc(sb + TAIL_HDR + c * 16384);
#pragma unroll
            for (int j = 0; j < 4; j++)
                mma_f16_ts(tmem, tmem + 128 + c * 32 + j * 8, wd + j * 2,
                           (c > 0 || j > 0) ? 1u : 0u);
        }
        tc_commit(sb + 24);
    }
    mbar_wait(sb + 24, 0);
    asm volatile("tcgen05.fence::after_thread_sync;" ::: "memory");

    bool cm = ((m & 1) == 0) && (g.maskB[m] == 0);     // PHASE = 0
    float cc0 = 0.f, cc1 = 0.f, cc2 = 0.f;
    if (!cm) { cc0 = g.coords[m*3]; cc1 = g.coords[m*3+1]; cc2 = g.coords[m*3+2]; }
    float raw[3] = {0.f, 0.f, 0.f};
    if (wid < 4) {
#pragma unroll
        for (int cb = 0; cb < 128; cb += 32) {
            uint32_t r32[32];
            TC_LD_X32(r32, tmem + cb);
            asm volatile("tcgen05.wait::ld.sync.aligned;" ::: "memory");
#pragma unroll
            for (int k = 0; k < 32; k++) {
                int col = cb + k;
                float v = __uint_as_float(r32[k]) + smf[784 + col];
                v = fmaf(cc0, smf[1040 + col * 3],     v);
                v = fmaf(cc1, smf[1040 + col * 3 + 1], v);
                v = fmaf(cc2, smf[1040 + col * 3 + 2], v);
                v = fmaxf(v, 0.f);
#pragma unroll
                for (int c = 0; c < 3; c++)
                    raw[c] = fmaf(v, smf[16 + col * 3 + c], raw[c]);
            }
        }
    }
    asm volatile("tcgen05.fence::before_thread_sync;" ::: "memory");

    cp_wait0();
    __syncthreads();
    if (tid == 0) {
        asm volatile("tcgen05.fence::after_thread_sync;" ::: "memory");
        asm volatile("fence.proxy.async.shared::cta;" ::: "memory");
#pragma unroll
        for (int c = 0; c < 2; c++) {
            uint64_t wd = mk_desc(sb + TAIL_HDR + 32768 + c * 16384);
#pragma unroll
            for (int j = 0; j < 4; j++)
                mma_f16_ts(tmem, tmem + 128 + c * 32 + j * 8, wd + j * 2,
                           (c > 0 || j > 0) ? 1u : 0u);
        }
        tc_commit(sb + 24);
    }
    mbar_wait(sb + 24, 1);
    asm volatile("tcgen05.fence::after_thread_sync;" ::: "memory");

    if (wid < 4) {
        float shf[3] = {0.f, 0.f, 0.f};
#pragma unroll
        for (int cb = 0; cb < 128; cb += 32) {
            uint32_t r32[32];
            TC_LD_X32(r32, tmem + cb);
            asm volatile("tcgen05.wait::ld.sync.aligned;" ::: "memory");
#pragma unroll
            for (int k = 0; k < 32; k++) {
                int col = cb + k;
                float v = __uint_as_float(r32[k]) + smf[912 + col];
                v = fmaf(cc0, smf[1424 + col * 3],     v);
                v = fmaf(cc1, smf[1424 + col * 3 + 1], v);
                v = fmaf(cc2, smf[1424 + col * 3 + 2], v);
                v = fmaxf(v, 0.f);
#pragma unroll
                for (int c = 0; c < 3; c++)
                    shf[c] = fmaf(v, smf[400 + col * 3 + c], shf[c]);
            }
        }
        float ld = 0.f;
#pragma unroll
        for (int c = 0; c < 3; c++) {
            float r = raw[c] + g.bs2[c];
            float s = shf[c] + g.bh2[c];
            float ls = cm ? tanhf(r) * 2.f : 0.f;
            ld += ls;
            float coord = g.coords[m * 3 + c];
            g.out[m * 3 + c] = cm ? (expf(ls) * coord + s) : coord;
        }
#pragma unroll
        for (int o = 16; o > 0; o >>= 1)
            ld += __shfl_xor_sync(0xFFFFFFFFu, ld, o);
        if (lid == 0) atomicAdd(&g.logdet[m >> 13], ld);
    }

    __syncthreads();
    if (wid == 0) {
        asm volatile("tcgen05.dealloc.cta_group::1.sync.aligned.b32 %0, %1;"
                     :: "r"(tmem), "r"(256u));
    }
#else
    if (threadIdx.x >= 128) return;
    const int m = blockIdx.x * 128 + threadIdx.x;
    const bool masked = (g.maskB[m] != 0);
    bool cm = ((m & 1) == 0) && !masked;
    float hrow[128];
    for (int cb = 0; cb < 128; cb++) {
        float acc = 0.f;
        for (int k = 0; k < 128; k++)
            acc = fmaf(__half2float(g.A1[(size_t)m * 128 + k]),
                       __half2float(g.Wt[(size_t)cb * 256 + k]), acc);
        for (int k = 0; k < 128; k++)
            acc = fmaf(__half2float(g.A2[(size_t)m * 128 + k]),
                       __half2float(g.Wt[(size_t)cb * 256 + 128 + k]), acc);
        float v = fmaxf(acc + g.bias[cb], 0.f);
        if (masked) v = 0.f;
        hrow[cb] = __half2float(__float2half(v));
    }
    float cc[3];
    for (int c = 0; c < 3; c++) cc[c] = cm ? 0.f : g.coords[m * 3 + c];
    float raw[3], shf[3];
    for (int c = 0; c < 3; c++) { raw[c] = g.bs2[c]; shf[c] = g.bh2[c]; }
    for (int n = 0; n < 128; n++) {
        float accs = g.bse[n], acch = g.bhe[n];
        for (int k = 0; k < 128; k++) {
            accs = fmaf(hrow[k], __half2float(g.Wse[(size_t)n * 192 + k]), accs);
            acch = fmaf(hrow[k], __half2float(g.Whe[(size_t)n * 192 + k]), acch);
        }
        for (int c = 0; c < 3; c++) {
            accs = fmaf(cc[c], __half2float(g.Wse[(size_t)n * 192 + 128 + c]), accs);
            acch = fmaf(cc[c], __half2float(g.Whe[(size_t)n * 192 + 128 + c]), acch);
        }
        accs = fmaxf(accs, 0.f); acch = fmaxf(acch, 0.f);
        for (int c = 0; c < 3; c++) {
            raw[c] = fmaf(accs, g.Ws2[n * 3 + c], raw[c]);
            shf[c] = fmaf(acch, g.Wh2[n * 3 + c], shf[c]);
        }
    }
    float ld = 0.f;
    for (int c = 0; c < 3; c++) {
        float ls = cm ? tanhf(raw[c]) * 2.f : 0.f;
        ld += ls;
        float coord = g.coords[m * 3 + c];
        g.out[m * 3 + c] = cm ? (expf(ls) * coord + shf[c]) : coord;
    }
    atomicAdd(&g.logdet[m >> 13], ld);
#endif
}

// ---------------------------------------------------------------------------
// Host launcher. Two-stream fork-join: CSR build overlaps k_fused_in.
// Streams/events created once (host resources, not device allocations);
// identical launch topology every call => graph-capture safe fork-join.
// ---------------------------------------------------------------------------
extern "C" void kernel_launch(void* const* d_in, const int* in_sizes, int n_in,
                              void* d_out, int out_size) {
    const float*         coords = (const float*)d_in[0];
    const int*           types  = (const int*)  d_in[1];
    const int*           adj    = (const int*)  d_in[2];
    const int*           ebi    = (const int*)  d_in[3];
    const unsigned char* maskB  = (const unsigned char*)d_in[4];
    const float* emb   = (const float*)d_in[5];
    const float* W_in  = (const float*)d_in[6];
    const float* b_in  = (const float*)d_in[7];
    const float* msg_W = (const float*)d_in[8];
    const float* msg_b = (const float*)d_in[9];
    const float* upd_W = (const float*)d_in[10];
    const float* upd_b = (const float*)d_in[11];
    const float* W_out = (const float*)d_in[12];
    const float* b_out = (const float*)d_in[13];
    const float* Ws1   = (const float*)d_in[14];
    const float* bs1   = (const float*)d_in[15];
    const float* Ws2   = (const float*)d_in[16];
    const float* bs2   = (const float*)d_in[17];
    const float* Wh1   = (const float*)d_in[18];
    const float* bh1   = (const float*)d_in[19];
    const float* Wh2   = (const float*)d_in[20];
    const float* bh2   = (const float*)d_in[21];

    float* out    = (float*)d_out;
    float* logdet = out + (size_t)BN_ * 3;

    __half *h, *b1, *b2, *wth;
    float *wt;
    int *off, *part, *cur, *srcl;
    cudaGetSymbolAddress((void**)&h,    g_h);
    cudaGetSymbolAddress((void**)&b1,   g_b1);
    cudaGetSymbolAddress((void**)&b2,   g_b2);
    cudaGetSymbolAddress((void**)&wt,   g_wt);
    cudaGetSymbolAddress((void**)&wth,  g_wth);
    cudaGetSymbolAddress((void**)&off,  g_off);
    cudaGetSymbolAddress((void**)&part, g_part);
    cudaGetSymbolAddress((void**)&cur,  g_cur);
    cudaGetSymbolAddress((void**)&srcl, g_srcl);

    cudaFuncSetAttribute(k_fused_in,   cudaFuncAttributeMaxDynamicSharedMemorySize, SMEM_FUSED);
    cudaFuncSetAttribute(k_fused_upd,  cudaFuncAttributeMaxDynamicSharedMemorySize, SMEM_FUSED);
    cudaFuncSetAttribute(k_fused_tail, cudaFuncAttributeMaxDynamicSharedMemorySize, SMEM_TAIL);

    // One-time side-stream + events (host resources; no device allocation).
    static cudaStream_t sB = 0;
    static cudaEvent_t  eA = 0, eB = 0;
    if (sB == 0) {
        cudaStreamCreateWithFlags(&sB, cudaStreamNonBlocking);
        cudaEventCreateWithFlags(&eA, cudaEventDisableTiming);
        cudaEventCreateWithFlags(&eB, cudaEventDisableTiming);
    }

    const int BT = 256;

    // s0: prep (produces weights + zeroed off/logdet)
    k_prep<<<1024, BT>>>(W_in, msg_W, upd_W, W_out, Ws1, Wh1, bs1, bh1, b_out,
                         wt, wth, off, logdet);
    cudaEventRecord(eA, 0);

    // sB: CSR build (needs only off zeroed by prep) — overlaps fused_in
    cudaStreamWaitEvent(sB, eA, 0);
    k_hist <<<E_ / BT, BT, 0, sB>>>(adj, ebi, off);
    k_scanA<<<512, 512, 0, sB>>>(off, part);
    k_scanB<<<512, 512, 0, sB>>>(off, part, cur);
    k_place<<<E_ / BT, BT, 0, sB>>>(adj, ebi, cur, srcl);
    cudaEventRecord(eB, sB);

    // s0: fused input + msg0 (M=256) — concurrent with CSR chain
    FIN fi{emb, types, coords, wt + O_WIN, b_in, maskB, h,
           wth + H_MSG0, msg_b, b1};
    k_fused_in<<<BN_ / 256, 256, SMEM_FUSED>>>(fi);

    // join: gather0 needs CSR (sB) + msg0 (s0)
    cudaStreamWaitEvent(0, eB, 0);
    k_gather<<<BN_ / 16, BT>>>(b1, off, srcl, b2);

    // fused upd0 + msg1 (M=256)
    FUP fu{h, b2, wth + H_UPD0, upd_b, maskB, h, wth + H_MSG1, msg_b + 128, b1};
    k_fused_upd<<<BN_ / 256, 256, SMEM_FUSED>>>(fu);

    // gather layer 1
    k_gather<<<BN_ / 16, BT>>>(b1, off, srcl, b2);

    // fused tail = upd1 + coupling
    FT ft{h, b2, wth + H_UPD1, upd_b + 128,
          wth + H_WSE, wth + H_WHE, wt + O_BSE, wt + O_BHE,
          Ws2, bs2, Wh2, bh2, coords, maskB, out, logdet};
    k_fused_tail<<<BN_ / 128, 256, SMEM_TAIL>>>(ft);
}